// round 8
// baseline (speedup 1.0000x reference)
#include <cuda_runtime.h>

// ---------------------------------------------------------------------------
// Single fused kernel. B=512, NQ=10, NA=4, T=16, DEG=4, LAYERS=2.
// State: q = i>>4 (10-bit query), t = i&15 (ancilla). Warp w owns t=w.
// In-warp: 1024 amps, 32 f32x2 regs/lane. Alternating qubit map:
//   qubit Q even -> register bit Q/2 ; qubit Q odd -> lane bit Q/2.
// ---------------------------------------------------------------------------

#define BATCH 512

typedef unsigned long long f2x;

// ---- f32x2 primitives ------------------------------------------------------
static __device__ __forceinline__ f2x f2pack(float lo, float hi) {
    f2x r; asm("mov.b64 %0, {%1, %2};" : "=l"(r) : "f"(lo), "f"(hi)); return r;
}
static __device__ __forceinline__ void f2unpack(f2x v, float& lo, float& hi) {
    asm("mov.b64 {%0, %1}, %2;" : "=f"(lo), "=f"(hi) : "l"(v));
}
static __device__ __forceinline__ f2x f2fma(f2x a, f2x b, f2x c) {
    f2x r; asm("fma.rn.f32x2 %0, %1, %2, %3;" : "=l"(r) : "l"(a), "l"(b), "l"(c)); return r;
}
static __device__ __forceinline__ f2x f2mul(f2x a, f2x b) {
    f2x r; asm("mul.rn.f32x2 %0, %1, %2;" : "=l"(r) : "l"(a), "l"(b)); return r;
}
static __device__ __forceinline__ f2x f2swap(f2x v) {
    float lo, hi; f2unpack(v, lo, hi); return f2pack(hi, lo);
}
static __device__ __forceinline__ f2x f2shfl(f2x v, int m) {
    float lo, hi; f2unpack(v, lo, hi);
    lo = __shfl_xor_sync(0xffffffffu, lo, m);
    hi = __shfl_xor_sync(0xffffffffu, hi, m);
    return f2pack(lo, hi);
}
static __device__ __forceinline__ f2x f2shflswap(f2x v, int m) {
    float lo, hi; f2unpack(v, lo, hi);
    lo = __shfl_xor_sync(0xffffffffu, lo, m);
    hi = __shfl_xor_sync(0xffffffffu, hi, m);
    return f2pack(hi, lo);
}
static __device__ __forceinline__ float2 cmulf(float2 a, float2 b) {
    return make_float2(a.x * b.x - a.y * b.y, a.x * b.y + a.y * b.x);
}

// ---- gates -----------------------------------------------------------------
// Paired ry: reg-qubit QR then lane-qubit QL, fused in one loop (order exact).
template <int QR, int QL>
static __device__ __forceinline__ void ry_pair_rl(f2x* s, float cR, float sR,
                                                  float cL, float sL, int lane) {
    constexpr int M = 1 << (QR / 2), L = 1 << (QL / 2);
    const f2x ccR = f2pack(cR, cR), spR = f2pack(sR, sR), nsR = f2pack(-sR, -sR);
    const f2x ccL = f2pack(cL, cL);
    const f2x tL  = (lane & L) ? f2pack(sL, sL) : f2pack(-sL, -sL);
#pragma unroll
    for (int r = 0; r < 32; ++r)
        if (!(r & M)) {
            f2x a = s[r], b = s[r | M];
            f2x na = f2fma(ccR, a, f2mul(nsR, b));
            f2x nb = f2fma(ccR, b, f2mul(spR, a));
            f2x oa = f2shfl(na, L);
            f2x ob = f2shfl(nb, L);
            s[r]     = f2fma(ccL, na, f2mul(tL, oa));
            s[r | M] = f2fma(ccL, nb, f2mul(tL, ob));
        }
}

// Paired ry: lane-qubit QL first, then reg-qubit QR (adjoint block order).
template <int QL, int QR>
static __device__ __forceinline__ void ry_pair_lr(f2x* s, float cL, float sL,
                                                  float cR, float sR, int lane) {
    constexpr int M = 1 << (QR / 2), L = 1 << (QL / 2);
    const f2x ccR = f2pack(cR, cR), spR = f2pack(sR, sR), nsR = f2pack(-sR, -sR);
    const f2x ccL = f2pack(cL, cL);
    const f2x tL  = (lane & L) ? f2pack(sL, sL) : f2pack(-sL, -sL);
#pragma unroll
    for (int r = 0; r < 32; ++r)
        if (!(r & M)) {
            f2x a = s[r], b = s[r | M];
            f2x na = f2fma(ccL, a, f2mul(tL, f2shfl(a, L)));
            f2x nb = f2fma(ccL, b, f2mul(tL, f2shfl(b, L)));
            s[r]     = f2fma(ccR, na, f2mul(nsR, nb));
            s[r | M] = f2fma(ccR, nb, f2mul(spR, na));
        }
}

// crx (ctrl=1): new = c*own + sn*(other.y, -other.x); pk = (sn, -sn).
template <int C, int TQ>
static __device__ __forceinline__ void crx_g(f2x* s, f2x cc, f2x pk, int lane) {
    if constexpr ((C & 1) == 0 && (TQ & 1) == 1) {        // reg ctrl, lane tgt
        constexpr int MC = 1 << (C / 2), LT = 1 << (TQ / 2);
#pragma unroll
        for (int r = 0; r < 32; ++r)
            if (r & MC) {  // compile-time per r: shfl warp-uniform
                f2x osw = f2shflswap(s[r], LT);
                s[r] = f2fma(cc, s[r], f2mul(pk, osw));
            }
    } else {                                              // lane ctrl, reg tgt: no shfl
        constexpr int LC = 1 << (C / 2), MT = 1 << (TQ / 2);
        const bool act = (lane & LC) != 0;
        const f2x cc2 = act ? cc : f2pack(1.f, 1.f);
        const f2x pk2 = act ? pk : 0ull;
#pragma unroll
        for (int r = 0; r < 32; ++r)
            if (!(r & MT)) {
                f2x a = s[r], b = s[r | MT];
                s[r]      = f2fma(cc2, a, f2mul(pk2, f2swap(b)));
                s[r | MT] = f2fma(cc2, b, f2mul(pk2, f2swap(a)));
            }
    }
}

// ---- gate-list macros (indices validated rounds 4-6) -----------------------
#define CRXF(C, T, I) { float2 g = cs[I]; f2x cc = f2pack(g.x, g.x), pk = f2pack(g.y, -g.y); \
                        crx_g<C, T>(s, cc, pk, lane); }
#define CRXA(C, T, I) { float2 g = cs[I]; f2x cc = f2pack(g.x, g.x), pk = f2pack(-g.y, g.y); \
                        crx_g<C, T>(s, cc, pk, lane); }
#define RYPF(QR, QL, IR, IL) { float2 gr = cs[IR], gl = cs[IL]; \
                               ry_pair_rl<QR, QL>(s, gr.x, gr.y, gl.x, gl.y, lane); }
#define RYPA(QL, QR, IL, IR) { float2 gl = cs[IL], gr = cs[IR]; \
                               ry_pair_lr<QL, QR>(s, gl.x, -gl.y, gr.x, -gr.y, lane); }

#define RING1_F() CRXF(9, 0, 10) CRXF(8, 9, 11) CRXF(7, 8, 12) CRXF(6, 7, 13) CRXF(5, 6, 14) \
                  CRXF(4, 5, 15) CRXF(3, 4, 16) CRXF(2, 3, 17) CRXF(1, 2, 18) CRXF(0, 1, 19)
#define RING2_F() CRXF(9, 8, 30) CRXF(0, 9, 31) CRXF(1, 0, 32) CRXF(2, 1, 33) CRXF(3, 2, 34) \
                  CRXF(4, 3, 35) CRXF(5, 4, 36) CRXF(6, 5, 37) CRXF(7, 6, 38) CRXF(8, 7, 39)
#define BLK1_F()  RYPF(0, 1, 0, 1) RYPF(2, 3, 2, 3) RYPF(4, 5, 4, 5) RYPF(6, 7, 6, 7) RYPF(8, 9, 8, 9)
#define MID_F()   RYPF(0, 1, 20, 21) RYPF(2, 3, 22, 23) RYPF(4, 5, 24, 25) RYPF(6, 7, 26, 27) RYPF(8, 9, 28, 29)

#define RING1_A() CRXA(0, 1, 19) CRXA(1, 2, 18) CRXA(2, 3, 17) CRXA(3, 4, 16) CRXA(4, 5, 15) \
                  CRXA(5, 6, 14) CRXA(6, 7, 13) CRXA(7, 8, 12) CRXA(8, 9, 11) CRXA(9, 0, 10)
#define RING2_A() CRXA(8, 7, 39) CRXA(7, 6, 38) CRXA(6, 5, 37) CRXA(5, 4, 36) CRXA(4, 3, 35) \
                  CRXA(3, 2, 34) CRXA(2, 1, 33) CRXA(1, 0, 32) CRXA(0, 9, 31) CRXA(9, 8, 30)
#define BLK1_A()  RYPA(9, 8, 9, 8) RYPA(7, 6, 7, 6) RYPA(5, 4, 5, 4) RYPA(3, 2, 3, 2) RYPA(1, 0, 1, 0)
#define MID_A()   RYPA(9, 8, 29, 28) RYPA(7, 6, 27, 26) RYPA(5, 4, 25, 24) RYPA(3, 2, 23, 22) RYPA(1, 0, 21, 20)

static __device__ __forceinline__ void run_layer_fwd(f2x* s, const float2* cs, int lane) {
    BLK1_F() RING1_F() MID_F() RING2_F()
}
static __device__ __forceinline__ void run_layer_fwd_tail(f2x* s, const float2* cs, int lane) {
    RING1_F() MID_F() RING2_F()
}
static __device__ __forceinline__ void run_layer_adj(f2x* s, const float2* cs, int lane) {
    RING2_A() MID_A() RING1_A() BLK1_A()
}

// ---- expectation values ----------------------------------------------------
template <int Q>
static __device__ __forceinline__ void expval_q(const f2x* s, int lane, float* acc) {
    float ax = 0.f, ay = 0.f, z = 0.f;
    if constexpr ((Q & 1) == 0) {
        constexpr int M = 1 << (Q / 2);
#pragma unroll
        for (int r = 0; r < 32; ++r)
            if (!(r & M)) {
                float axr, ayr, bxr, byr;
                f2unpack(s[r], axr, ayr);
                f2unpack(s[r | M], bxr, byr);
                ax = fmaf(axr, bxr, fmaf(ayr, byr, ax));
                ay = fmaf(axr, byr, fmaf(-ayr, bxr, ay));
                z  = fmaf(axr, axr, fmaf(ayr, ayr, fmaf(-bxr, bxr, fmaf(-byr, byr, z))));
            }
    } else {
        constexpr int L = 1 << (Q / 2);
        const bool lo = (lane & L) == 0;
#pragma unroll
        for (int r = 0; r < 32; ++r) {
            float x, y;
            f2unpack(s[r], x, y);
            float ox = __shfl_xor_sync(0xffffffffu, x, L);
            float oy = __shfl_xor_sync(0xffffffffu, y, L);
            float n = fmaf(x, x, y * y);
            if (lo) {
                ax = fmaf(x, ox, fmaf(y, oy, ax));
                ay = fmaf(x, oy, fmaf(-y, ox, ay));
                z += n;
            } else {
                z -= n;
            }
        }
    }
#pragma unroll
    for (int off = 16; off; off >>= 1) {
        ax += __shfl_xor_sync(0xffffffffu, ax, off);
        ay += __shfl_xor_sync(0xffffffffu, ay, off);
        z  += __shfl_xor_sync(0xffffffffu, z, off);
    }
    if (lane == 0) {
        atomicAdd(&acc[Q], 2.f * ax);
        atomicAdd(&acc[10 + Q], 2.f * ay);
        atomicAdd(&acc[20 + Q], z);
    }
}

// ---------------------------------------------------------------------------
// Ancilla mix (16x16 across warps via smem; column-owned, race-free)
// ---------------------------------------------------------------------------
static __device__ __forceinline__ void ancilla_mix(f2x* s, f2x* buf, const ulonglong2* Mk,
                                                   int w, int lane) {
#pragma unroll
    for (int r = 0; r < 32; ++r) buf[w * 1024 + r * 32 + lane] = s[r];
    __syncthreads();
#pragma unroll 1
    for (int half = 0; half < 2; ++half) {
        int q = w * 64 + half * 32 + lane;
        f2x in[16], insw[16];
#pragma unroll
        for (int t = 0; t < 16; ++t) {
            in[t] = buf[t * 1024 + q];
            float ix, iy;
            f2unpack(in[t], ix, iy);
            insw[t] = f2pack(-iy, ix);
        }
#pragma unroll
        for (int tp = 0; tp < 16; ++tp) {
            f2x a = 0ull;
#pragma unroll
            for (int t = 0; t < 16; ++t) {
                ulonglong2 m = Mk[tp * 16 + t];
                a = f2fma(m.x, in[t], a);
                a = f2fma(m.y, insw[t], a);
            }
            buf[tp * 1024 + q] = a;
        }
    }
    __syncthreads();
#pragma unroll
    for (int r = 0; r < 32; ++r) s[r] = buf[w * 1024 + r * 32 + lane];
}

// ---------------------------------------------------------------------------
// Fused mega-kernel: setup + projection + circuit, one CTA per batch element.
// ---------------------------------------------------------------------------
__global__ __launch_bounds__(512, 1) void qts_main(
    const float* __restrict__ x, const float* __restrict__ Wp,
    const float* __restrict__ bp, const float* __restrict__ prep,
    const float* __restrict__ sig, const float* __restrict__ qff,
    const float* __restrict__ Wout, const float* __restrict__ bout,
    float* __restrict__ out) {
    extern __shared__ char smem_raw[];
    f2x* buf         = (f2x*)smem_raw;                        // [16][1024] (131072 B)
    ulonglong2* sMpk = (ulonglong2*)(smem_raw + 131072);      // [3][256]   (12288 B)
    float2* sa       = (float2*)(smem_raw + 131072 + 12288);  // [16][80]   (10240 B)
    float2* sqff     = sa + 1280;                             // [40]
    float2* sv0      = sqff + 40;                             // [16]
    float* acc       = (float*)(sv0 + 16);                    // [32]
    // Projection/setup scratch ALIASED inside buf (unused until the circuit):
    float* WsT  = (float*)smem_raw;                 // [64][80] W transposed (20480 B)
    float* xe   = (float*)(smem_raw + 20480);       // [16][64] (4096 B)
    float2* U   = (float2*)(smem_raw + 24576);      // [16][16] prepare unitary (2048 B)

    const int tid = threadIdx.x, b = blockIdx.x;
    const int w = tid >> 5, lane = tid & 31;

    // ---- phase 1: load W^T, x+pe; build U columns (threads 0-15) ----
    for (int i = tid; i < 80 * 64; i += 512) {
        int j = i / 64, f = i % 64;
        WsT[f * 80 + j] = Wp[i];
    }
    const float kdiv = -0.14391156831212787f;  // -ln(10000)/64
    for (int i = tid; i < 1024; i += 512) {
        int f = i >> 4, t = i & 15;
        float arg = (float)t * expf(kdiv * (float)(f & ~1));
        float pe = (f & 1) ? cosf(arg) : sinf(arg);
        xe[t * 64 + f] = x[b * 1024 + i] + pe;
    }
    if (tid < 16) {
        float2 v[16];
        for (int t = 0; t < 16; ++t) v[t] = make_float2(t == tid ? 1.f : 0.f, 0.f);
        for (int ly = 0; ly < 4; ++ly) {
            for (int qi = 0; qi < 4; ++qi) {
                int m = 1 << (3 - qi);
                float th = prep[(ly * 4 + qi) * 2 + 0];
                float c, sn;
                sincosf(0.5f * th, &sn, &c);
                for (int j = 0; j < 16; ++j)
                    if (!(j & m)) {
                        float2 a0 = v[j], a1 = v[j | m];
                        v[j]     = make_float2(c * a0.x - sn * a1.x, c * a0.y - sn * a1.y);
                        v[j | m] = make_float2(sn * a0.x + c * a1.x, sn * a0.y + c * a1.y);
                    }
                th = prep[(ly * 4 + qi) * 2 + 1];
                sincosf(0.5f * th, &sn, &c);
                float2 e0 = make_float2(c, -sn), e1 = make_float2(c, sn);
                for (int j = 0; j < 16; ++j) v[j] = cmulf(v[j], (j & m) ? e1 : e0);
            }
            for (int i = 0; i < 3; ++i) {
                int cm = 1 << (3 - i), tm = 1 << (2 - i);
                for (int j = 0; j < 16; ++j)
                    if ((j & cm) && !(j & tm)) {
                        float2 tmp = v[j]; v[j] = v[j | tm]; v[j | tm] = tmp;
                    }
            }
        }
        for (int t = 0; t < 16; ++t) U[t * 16 + tid] = v[t];
    }
    __syncthreads();

    // ---- phase 2: v0/qff/M_k constants + projection ----
    if (tid < 16) {
        float c, sn;
        sincosf(sig[0], &sn, &c);
        sv0[tid] = cmulf(make_float2(c, sn), U[tid * 16 + 0]);
    }
    if (tid < 40) {
        float c, sn;
        sincosf(0.5f * qff[tid], &sn, &c);
        sqff[tid] = make_float2(c, sn);
    }
    if (tid < 30) acc[tid] = 0.f;
    if (tid < 256) {
        int tp = tid >> 4, t = tid & 15;
        for (int m = 0; m < 3; ++m) {
            float c, sn;
            sincosf(sig[m + 1], &sn, &c);
            float2 a2 = make_float2(0.f, 0.f);
            for (int si = 0; si < 16; ++si) {
                float2 P = (si == 0) ? make_float2(c, sn) : make_float2(c, -sn);
                float2 u = U[tp * 16 + si];
                float2 uc = make_float2(U[t * 16 + si].x, -U[t * 16 + si].y);
                float2 p = cmulf(cmulf(u, P), uc);
                a2.x += p.x; a2.y += p.y;
            }
            sMpk[m * 256 + tp * 16 + t] =
                make_ulonglong2(f2pack(a2.x, a2.x), f2pack(a2.y, a2.y));
        }
    }
    // projection: 1280 angles for this batch (reads WsT/xe, writes sa)
    for (int o = tid; o < 1280; o += 512) {
        int t = o / 80, j = o % 80;
        float h = bp[j];
#pragma unroll 16
        for (int f = 0; f < 64; ++f) h = fmaf(xe[t * 64 + f], WsT[f * 80 + j], h);
        float half = 3.14159265358979323846f / (1.0f + expf(-h));
        float c, sn;
        sincosf(half, &sn, &c);
        sa[o] = make_float2(c, sn);
    }
    __syncthreads();
    // (buf region free from here on)

    const float2* cs = sa + w * 80;
    f2x s[32];

    // select k=0: first ry block on |0..0> is an exact product state (peel)
    {
        float lp = 1.f;
#pragma unroll
        for (int j = 0; j < 5; ++j) {
            float2 g = cs[2 * j + 1];
            lp *= ((lane >> j) & 1) ? g.y : g.x;
        }
        float rp[32];
        rp[0] = lp;
#pragma unroll
        for (int j = 0; j < 5; ++j) {
            float2 g = cs[2 * j];
            int m = 1 << j;
#pragma unroll
            for (int r = 0; r < 32; ++r)
                if (r < m) {
                    rp[r | m] = rp[r] * g.y;
                    rp[r]     = rp[r] * g.x;
                }
        }
        float2 v = sv0[w];
#pragma unroll
        for (int r = 0; r < 32; ++r) s[r] = f2pack(v.x * rp[r], v.y * rp[r]);

        run_layer_fwd_tail(s, cs, lane);
        run_layer_fwd(s, cs + 40, lane);
    }
    ancilla_mix(s, buf, sMpk + 0 * 256, w, lane);

#pragma unroll 1
    for (int k = 1; k < 4; ++k) {
        const bool adj = (k & 1) != 0;
#pragma unroll 1
        for (int l = 0; l < 2; ++l) {
            const float2* lcs = cs + (adj ? (1 - l) : l) * 40;
            if (adj) run_layer_adj(s, lcs, lane);
            else     run_layer_fwd(s, lcs, lane);
        }
        if (k < 3) ancilla_mix(s, buf, sMpk + k * 256, w, lane);
    }

    run_layer_fwd(s, sqff, lane);  // qff (shared params)

    expval_q<0>(s, lane, acc);
    expval_q<1>(s, lane, acc);
    expval_q<2>(s, lane, acc);
    expval_q<3>(s, lane, acc);
    expval_q<4>(s, lane, acc);
    expval_q<5>(s, lane, acc);
    expval_q<6>(s, lane, acc);
    expval_q<7>(s, lane, acc);
    expval_q<8>(s, lane, acc);
    expval_q<9>(s, lane, acc);
    __syncthreads();

    if (tid == 0) {
        float o = bout[0];
#pragma unroll
        for (int i = 0; i < 30; ++i) o = fmaf(acc[i], Wout[i], o);
        out[b] = o;
    }
}

// ---------------------------------------------------------------------------
extern "C" void kernel_launch(void* const* d_in, const int* in_sizes, int n_in,
                              void* d_out, int out_size) {
    (void)in_sizes; (void)n_in; (void)out_size;
    const float* x    = (const float*)d_in[0];
    const float* Wp   = (const float*)d_in[1];
    const float* bp   = (const float*)d_in[2];
    const float* prep = (const float*)d_in[3];
    const float* sig  = (const float*)d_in[4];
    const float* qff  = (const float*)d_in[5];
    const float* Wout = (const float*)d_in[6];
    const float* bout = (const float*)d_in[7];
    float* out = (float*)d_out;

    size_t smem = 131072 + 12288 + 10240 + 40 * 8 + 16 * 8 + 32 * 4;
    cudaFuncSetAttribute(qts_main, cudaFuncAttributeMaxDynamicSharedMemorySize, (int)smem);

    qts_main<<<BATCH, 512, smem>>>(x, Wp, bp, prep, sig, qff, Wout, bout, out);
}

// round 9
// speedup vs baseline: 1.2948x; 1.2948x over previous
#include <cuda_runtime.h>

// ---------------------------------------------------------------------------
// B=512, NQ=10, NA=4, T=16, DEG=4, LAYERS=2, F=64, NROTS=80, QFF_NROTS=40
// State: q = i>>4 (10-bit query), t = i&15 (ancilla). Warp w owns t=w.
// In-warp: 1024 amps, 32 f32x2 regs/lane. Alternating qubit map:
//   qubit Q even -> register bit Q/2 ; qubit Q odd -> lane bit Q/2.
// Ancilla mix M_k = U P_k U^dag = alpha_k I + beta_k u0 u0^dag  (rank-1!)
//   alpha = e^{-i phi}, beta = 2i sin(phi), u0 = U_prep[:,0].
// ---------------------------------------------------------------------------

#define BATCH 512

typedef unsigned long long f2x;

__device__ float2 g_cs[BATCH * 1280];  // (cos,sin) half-angles per (b,t,gate)
__device__ float2 g_qffcs[40];
__device__ float2 g_v0[16];            // e^{i phi0} * U[:,0]
__device__ float2 g_u0[16];            // U[:,0]
__device__ float4 g_ab[3];             // (cos phi, -sin phi, 2 sin phi, 0) for k=1..3

// ---- f32x2 primitives ------------------------------------------------------
static __device__ __forceinline__ f2x f2pack(float lo, float hi) {
    f2x r; asm("mov.b64 %0, {%1, %2};" : "=l"(r) : "f"(lo), "f"(hi)); return r;
}
static __device__ __forceinline__ void f2unpack(f2x v, float& lo, float& hi) {
    asm("mov.b64 {%0, %1}, %2;" : "=f"(lo), "=f"(hi) : "l"(v));
}
static __device__ __forceinline__ f2x f2fma(f2x a, f2x b, f2x c) {
    f2x r; asm("fma.rn.f32x2 %0, %1, %2, %3;" : "=l"(r) : "l"(a), "l"(b), "l"(c)); return r;
}
static __device__ __forceinline__ f2x f2mul(f2x a, f2x b) {
    f2x r; asm("mul.rn.f32x2 %0, %1, %2;" : "=l"(r) : "l"(a), "l"(b)); return r;
}
static __device__ __forceinline__ f2x f2add(f2x a, f2x b) {
    f2x r; asm("add.rn.f32x2 %0, %1, %2;" : "=l"(r) : "l"(a), "l"(b)); return r;
}
static __device__ __forceinline__ f2x f2swap(f2x v) {
    float lo, hi; f2unpack(v, lo, hi); return f2pack(hi, lo);
}
static __device__ __forceinline__ f2x f2shfl(f2x v, int m) {
    float lo, hi; f2unpack(v, lo, hi);
    lo = __shfl_xor_sync(0xffffffffu, lo, m);
    hi = __shfl_xor_sync(0xffffffffu, hi, m);
    return f2pack(lo, hi);
}
static __device__ __forceinline__ f2x f2shflswap(f2x v, int m) {
    float lo, hi; f2unpack(v, lo, hi);
    lo = __shfl_xor_sync(0xffffffffu, lo, m);
    hi = __shfl_xor_sync(0xffffffffu, hi, m);
    return f2pack(hi, lo);
}
static __device__ __forceinline__ float2 cmulf(float2 a, float2 b) {
    return make_float2(a.x * b.x - a.y * b.y, a.x * b.y + a.y * b.x);
}

// ---- gates (round-6 versions; measured best) --------------------------------
template <int Q>
static __device__ __forceinline__ void ry_g(f2x* s, f2x cc, f2x sp, f2x ns, int lane) {
    if constexpr ((Q & 1) == 0) {
        constexpr int M = 1 << (Q / 2);
#pragma unroll
        for (int r = 0; r < 32; ++r)
            if (!(r & M)) {
                f2x a = s[r], b = s[r | M];
                s[r]     = f2fma(cc, a, f2mul(ns, b));
                s[r | M] = f2fma(cc, b, f2mul(sp, a));
            }
    } else {
        constexpr int L = 1 << (Q / 2);
        const f2x t = (lane & L) ? sp : ns;
#pragma unroll
        for (int r = 0; r < 32; ++r) {
            f2x o = f2shfl(s[r], L);
            s[r] = f2fma(cc, s[r], f2mul(t, o));
        }
    }
}

// crx (ctrl=1): new = c*own + sn*(other.y, -other.x); pk = (sn, -sn).
template <int C, int TQ>
static __device__ __forceinline__ void crx_g(f2x* s, f2x cc, f2x pk, int lane) {
    if constexpr ((C & 1) == 0 && (TQ & 1) == 1) {        // reg ctrl, lane tgt
        constexpr int MC = 1 << (C / 2), LT = 1 << (TQ / 2);
#pragma unroll
        for (int r = 0; r < 32; ++r)
            if (r & MC) {  // compile-time per r: shfl warp-uniform
                f2x osw = f2shflswap(s[r], LT);
                s[r] = f2fma(cc, s[r], f2mul(pk, osw));
            }
    } else {                                              // lane ctrl, reg tgt: no shfl
        constexpr int LC = 1 << (C / 2), MT = 1 << (TQ / 2);
        const bool act = (lane & LC) != 0;
        const f2x cc2 = act ? cc : f2pack(1.f, 1.f);
        const f2x pk2 = act ? pk : 0ull;
#pragma unroll
        for (int r = 0; r < 32; ++r)
            if (!(r & MT)) {
                f2x a = s[r], b = s[r | MT];
                s[r]      = f2fma(cc2, a, f2mul(pk2, f2swap(b)));
                s[r | MT] = f2fma(cc2, b, f2mul(pk2, f2swap(a)));
            }
    }
}

// sim14 layer gate lists (validated rounds 4-6)
#define GATES_RING1(CRXM)                                                        \
    CRXM(9, 0, 10) CRXM(8, 9, 11) CRXM(7, 8, 12) CRXM(6, 7, 13) CRXM(5, 6, 14)  \
    CRXM(4, 5, 15) CRXM(3, 4, 16) CRXM(2, 3, 17) CRXM(1, 2, 18) CRXM(0, 1, 19)

#define GATES_TAIL(RYM, CRXM)                                                    \
    GATES_RING1(CRXM)                                                            \
    RYM(0, 20) RYM(1, 21) RYM(2, 22) RYM(3, 23) RYM(4, 24)                       \
    RYM(5, 25) RYM(6, 26) RYM(7, 27) RYM(8, 28) RYM(9, 29)                       \
    CRXM(9, 8, 30) CRXM(0, 9, 31) CRXM(1, 0, 32) CRXM(2, 1, 33) CRXM(3, 2, 34)  \
    CRXM(4, 3, 35) CRXM(5, 4, 36) CRXM(6, 5, 37) CRXM(7, 6, 38) CRXM(8, 7, 39)

#define GATES_FWD(RYM, CRXM)                                                     \
    RYM(0, 0) RYM(1, 1) RYM(2, 2) RYM(3, 3) RYM(4, 4)                            \
    RYM(5, 5) RYM(6, 6) RYM(7, 7) RYM(8, 8) RYM(9, 9)                            \
    GATES_TAIL(RYM, CRXM)

#define GATES_ADJ(RYM, CRXM)                                                     \
    CRXM(8, 7, 39) CRXM(7, 6, 38) CRXM(6, 5, 37) CRXM(5, 4, 36) CRXM(4, 3, 35)  \
    CRXM(3, 2, 34) CRXM(2, 1, 33) CRXM(1, 0, 32) CRXM(0, 9, 31) CRXM(9, 8, 30)  \
    RYM(9, 29) RYM(8, 28) RYM(7, 27) RYM(6, 26) RYM(5, 25)                       \
    RYM(4, 24) RYM(3, 23) RYM(2, 22) RYM(1, 21) RYM(0, 20)                       \
    CRXM(0, 1, 19) CRXM(1, 2, 18) CRXM(2, 3, 17) CRXM(3, 4, 16) CRXM(4, 5, 15)  \
    CRXM(5, 6, 14) CRXM(6, 7, 13) CRXM(7, 8, 12) CRXM(8, 9, 11) CRXM(9, 0, 10)  \
    RYM(9, 9) RYM(8, 8) RYM(7, 7) RYM(6, 6) RYM(5, 5)                            \
    RYM(4, 4) RYM(3, 3) RYM(2, 2) RYM(1, 1) RYM(0, 0)

#define RYM_F(Q, I)  { float2 g = cs[I]; f2x cc = f2pack(g.x, g.x), sp = f2pack(g.y, g.y), \
                       ns = f2pack(-g.y, -g.y); ry_g<Q>(s, cc, sp, ns, lane); }
#define RYM_A(Q, I)  { float2 g = cs[I]; f2x cc = f2pack(g.x, g.x), sp = f2pack(-g.y, -g.y), \
                       ns = f2pack(g.y, g.y); ry_g<Q>(s, cc, sp, ns, lane); }
#define CRXM_F(C, T, I) { float2 g = cs[I]; f2x cc = f2pack(g.x, g.x), pk = f2pack(g.y, -g.y); \
                          crx_g<C, T>(s, cc, pk, lane); }
#define CRXM_A(C, T, I) { float2 g = cs[I]; f2x cc = f2pack(g.x, g.x), pk = f2pack(-g.y, g.y); \
                          crx_g<C, T>(s, cc, pk, lane); }

static __device__ __forceinline__ void run_layer_fwd(f2x* s, const float2* cs, int lane) {
    GATES_FWD(RYM_F, CRXM_F)
}
static __device__ __forceinline__ void run_layer_fwd_tail(f2x* s, const float2* cs, int lane) {
    GATES_TAIL(RYM_F, CRXM_F)
}
static __device__ __forceinline__ void run_layer_adj(f2x* s, const float2* cs, int lane) {
    GATES_ADJ(RYM_A, CRXM_A)
}

// ---- expectation values ----------------------------------------------------
template <int Q>
static __device__ __forceinline__ void expval_q(const f2x* s, int lane, float* acc) {
    float ax = 0.f, ay = 0.f, z = 0.f;
    if constexpr ((Q & 1) == 0) {
        constexpr int M = 1 << (Q / 2);
#pragma unroll
        for (int r = 0; r < 32; ++r)
            if (!(r & M)) {
                float axr, ayr, bxr, byr;
                f2unpack(s[r], axr, ayr);
                f2unpack(s[r | M], bxr, byr);
                ax = fmaf(axr, bxr, fmaf(ayr, byr, ax));
                ay = fmaf(axr, byr, fmaf(-ayr, bxr, ay));
                z  = fmaf(axr, axr, fmaf(ayr, ayr, fmaf(-bxr, bxr, fmaf(-byr, byr, z))));
            }
    } else {
        constexpr int L = 1 << (Q / 2);
        const bool lo = (lane & L) == 0;
#pragma unroll
        for (int r = 0; r < 32; ++r) {
            float x, y;
            f2unpack(s[r], x, y);
            float ox = __shfl_xor_sync(0xffffffffu, x, L);
            float oy = __shfl_xor_sync(0xffffffffu, y, L);
            float n = fmaf(x, x, y * y);
            if (lo) {
                ax = fmaf(x, ox, fmaf(y, oy, ax));
                ay = fmaf(x, oy, fmaf(-y, ox, ay));
                z += n;
            } else {
                z -= n;
            }
        }
    }
#pragma unroll
    for (int off = 16; off; off >>= 1) {
        ax += __shfl_xor_sync(0xffffffffu, ax, off);
        ay += __shfl_xor_sync(0xffffffffu, ay, off);
        z  += __shfl_xor_sync(0xffffffffu, z, off);
    }
    if (lane == 0) {
        atomicAdd(&acc[Q], 2.f * ax);
        atomicAdd(&acc[10 + Q], 2.f * ay);
        atomicAdd(&acc[20 + Q], z);
    }
}

// ---------------------------------------------------------------------------
// Projection kernel (circuit-constant setup in block 0) — round-6 structure
// ---------------------------------------------------------------------------
__global__ void qts_proj(const float* __restrict__ x, const float* __restrict__ Wp,
                         const float* __restrict__ bp, const float* __restrict__ prep,
                         const float* __restrict__ sig, const float* __restrict__ qff) {
    __shared__ float xe[16][64];
    __shared__ float WsT[64][80];
    __shared__ float2 U[16][16];
    int b = blockIdx.x, tid = threadIdx.x;

    if (b == 0) {
        if (tid < 16) {
            float2 v[16];
            for (int t = 0; t < 16; ++t) v[t] = make_float2(t == tid ? 1.f : 0.f, 0.f);
            for (int ly = 0; ly < 4; ++ly) {
                for (int qi = 0; qi < 4; ++qi) {
                    int m = 1 << (3 - qi);
                    float th = prep[(ly * 4 + qi) * 2 + 0];
                    float c, sn;
                    sincosf(0.5f * th, &sn, &c);
                    for (int j = 0; j < 16; ++j)
                        if (!(j & m)) {
                            float2 a0 = v[j], a1 = v[j | m];
                            v[j]     = make_float2(c * a0.x - sn * a1.x, c * a0.y - sn * a1.y);
                            v[j | m] = make_float2(sn * a0.x + c * a1.x, sn * a0.y + c * a1.y);
                        }
                    th = prep[(ly * 4 + qi) * 2 + 1];
                    sincosf(0.5f * th, &sn, &c);
                    float2 e0 = make_float2(c, -sn), e1 = make_float2(c, sn);
                    for (int j = 0; j < 16; ++j) v[j] = cmulf(v[j], (j & m) ? e1 : e0);
                }
                for (int i = 0; i < 3; ++i) {
                    int cm = 1 << (3 - i), tm = 1 << (2 - i);
                    for (int j = 0; j < 16; ++j)
                        if ((j & cm) && !(j & tm)) {
                            float2 tmp = v[j]; v[j] = v[j | tm]; v[j | tm] = tmp;
                        }
                }
            }
            for (int t = 0; t < 16; ++t) U[t][tid] = v[t];
        }
        __syncthreads();
        if (tid < 16) {
            float c, sn;
            sincosf(sig[0], &sn, &c);
            g_v0[tid] = cmulf(make_float2(c, sn), U[tid][0]);
            g_u0[tid] = U[tid][0];
        }
        if (tid < 40) {
            float c, sn;
            sincosf(0.5f * qff[tid], &sn, &c);
            g_qffcs[tid] = make_float2(c, sn);
        }
        if (tid < 3) {
            float c, sn;
            sincosf(sig[tid + 1], &sn, &c);
            g_ab[tid] = make_float4(c, -sn, 2.f * sn, 0.f);
        }
        __syncthreads();
    }

    for (int i = tid; i < 80 * 64; i += 256) {
        int j = i / 64, f = i % 64;
        WsT[f][j] = Wp[i];
    }
    const float kdiv = -0.14391156831212787f;  // -ln(10000)/64
    for (int i = tid; i < 1024; i += 256) {
        int f = i >> 4, t = i & 15;
        float arg = (float)t * expf(kdiv * (float)(f & ~1));
        float pe = (f & 1) ? cosf(arg) : sinf(arg);
        xe[t][f] = x[b * 1024 + i] + pe;
    }
    __syncthreads();

    for (int o = tid; o < 1280; o += 256) {
        int t = o / 80, j = o % 80;
        float h = bp[j];
#pragma unroll 16
        for (int f = 0; f < 64; ++f) h = fmaf(xe[t][f], WsT[f][j], h);
        float half = 3.14159265358979323846f / (1.0f + expf(-h));
        float c, sn;
        sincosf(half, &sn, &c);
        g_cs[b * 1280 + o] = make_float2(c, sn);
    }
}

// ---------------------------------------------------------------------------
// Rank-1 ancilla mix: s <- alpha*s + (beta*u0[w]) * dot, dot[q] = sum_t conj(u0[t])*s_t[q]
// ---------------------------------------------------------------------------
static __device__ __forceinline__ void ancilla_mix_r1(f2x* s, f2x* buf, f2x* dot,
                                                      float2 u0w, float2 alpha, float b2s,
                                                      int w, int lane, int tid) {
    // weighted store: conj(u0[w]) * s ; conj = (ur, -ui) -> cc=(ur,ur), pk=(ui,-ui)
    const f2x ccW = f2pack(u0w.x, u0w.x);
    const f2x pkW = f2pack(u0w.y, -u0w.y);
#pragma unroll
    for (int r = 0; r < 32; ++r)
        buf[w * 1024 + r * 32 + lane] = f2fma(ccW, s[r], f2mul(pkW, f2swap(s[r])));
    __syncthreads();
    // column sums: thread handles q = tid and q = tid + 512
#pragma unroll 1
    for (int h = 0; h < 2; ++h) {
        int q = h * 512 + tid;
        f2x a = buf[q];
#pragma unroll
        for (int t = 1; t < 16; ++t) a = f2add(a, buf[t * 1024 + q]);
        dot[q] = a;
    }
    __syncthreads();
    // apply: gamma = (i*b2s) * u0[w] = (-b2s*ui, b2s*ur)
    const float gr = -b2s * u0w.y, gi = b2s * u0w.x;
    const f2x ccA = f2pack(alpha.x, alpha.x), pkA = f2pack(-alpha.y, alpha.y);
    const f2x ccG = f2pack(gr, gr), pkG = f2pack(-gi, gi);
#pragma unroll
    for (int r = 0; r < 32; ++r) {
        f2x d = dot[r * 32 + lane];
        f2x t = f2fma(ccG, d, f2mul(pkG, f2swap(d)));
        s[r] = f2fma(ccA, s[r], f2fma(pkA, f2swap(s[r]), t));
    }
}

// ---------------------------------------------------------------------------
// Main kernel: one CTA per batch element; warp w owns ancilla slice t=w.
// ---------------------------------------------------------------------------
__global__ __launch_bounds__(512, 1) void qts_main(const float* __restrict__ Wout,
                                                   const float* __restrict__ bout,
                                                   float* __restrict__ out) {
    extern __shared__ char smem_raw[];
    f2x* buf     = (f2x*)smem_raw;                        // [16][1024] (131072 B)
    f2x* dot     = (f2x*)(smem_raw + 131072);             // [1024] (8192 B)
    float2* sa   = (float2*)(smem_raw + 131072 + 8192);   // [16][80] (10240 B)
    float2* sqff = sa + 1280;                             // [40]
    float2* sv0  = sqff + 40;                             // [16]
    float2* su0  = sv0 + 16;                              // [16]
    float4* sab  = (float4*)(su0 + 16);                   // [3]
    float* acc   = (float*)(sab + 3);                     // [32]

    const int tid = threadIdx.x, b = blockIdx.x;
    const int w = tid >> 5, lane = tid & 31;

    for (int i = tid; i < 1280; i += 512) sa[i] = g_cs[b * 1280 + i];
    if (tid < 40) sqff[tid] = g_qffcs[tid];
    if (tid < 16) { sv0[tid] = g_v0[tid]; su0[tid] = g_u0[tid]; }
    if (tid < 3) sab[tid] = g_ab[tid];
    if (tid < 30) acc[tid] = 0.f;
    __syncthreads();

    const float2* cs = sa + w * 80;
    const float2 u0w = su0[w];
    f2x s[32];

    // select k=0: first ry block on |0..0> is an exact product state (peel)
    {
        float lp = 1.f;
#pragma unroll
        for (int j = 0; j < 5; ++j) {
            float2 g = cs[2 * j + 1];
            lp *= ((lane >> j) & 1) ? g.y : g.x;
        }
        float rp[32];
        rp[0] = lp;
#pragma unroll
        for (int j = 0; j < 5; ++j) {
            float2 g = cs[2 * j];
            int m = 1 << j;
#pragma unroll
            for (int r = 0; r < 32; ++r)
                if (r < m) {
                    rp[r | m] = rp[r] * g.y;
                    rp[r]     = rp[r] * g.x;
                }
        }
        float2 v = sv0[w];
#pragma unroll
        for (int r = 0; r < 32; ++r) s[r] = f2pack(v.x * rp[r], v.y * rp[r]);

        run_layer_fwd_tail(s, cs, lane);
        run_layer_fwd(s, cs + 40, lane);
    }
    {
        float4 ab = sab[0];
        ancilla_mix_r1(s, buf, dot, u0w, make_float2(ab.x, ab.y), ab.z, w, lane, tid);
    }

#pragma unroll 1
    for (int k = 1; k < 4; ++k) {
        const bool adj = (k & 1) != 0;
#pragma unroll 1
        for (int l = 0; l < 2; ++l) {
            const float2* lcs = cs + (adj ? (1 - l) : l) * 40;
            if (adj) run_layer_adj(s, lcs, lane);
            else     run_layer_fwd(s, lcs, lane);
        }
        if (k < 3) {
            float4 ab = sab[k];
            ancilla_mix_r1(s, buf, dot, u0w, make_float2(ab.x, ab.y), ab.z, w, lane, tid);
        }
    }

    run_layer_fwd(s, sqff, lane);  // qff (shared params)

    expval_q<0>(s, lane, acc);
    expval_q<1>(s, lane, acc);
    expval_q<2>(s, lane, acc);
    expval_q<3>(s, lane, acc);
    expval_q<4>(s, lane, acc);
    expval_q<5>(s, lane, acc);
    expval_q<6>(s, lane, acc);
    expval_q<7>(s, lane, acc);
    expval_q<8>(s, lane, acc);
    expval_q<9>(s, lane, acc);
    __syncthreads();

    if (tid == 0) {
        float o = bout[0];
#pragma unroll
        for (int i = 0; i < 30; ++i) o = fmaf(acc[i], Wout[i], o);
        out[b] = o;
    }
}

// ---------------------------------------------------------------------------
extern "C" void kernel_launch(void* const* d_in, const int* in_sizes, int n_in,
                              void* d_out, int out_size) {
    (void)in_sizes; (void)n_in; (void)out_size;
    const float* x    = (const float*)d_in[0];
    const float* Wp   = (const float*)d_in[1];
    const float* bp   = (const float*)d_in[2];
    const float* prep = (const float*)d_in[3];
    const float* sig  = (const float*)d_in[4];
    const float* qff  = (const float*)d_in[5];
    const float* Wout = (const float*)d_in[6];
    const float* bout = (const float*)d_in[7];
    float* out = (float*)d_out;

    size_t smem = 131072 + 8192 + 10240 + 40 * 8 + 16 * 8 + 16 * 8 + 3 * 16 + 32 * 4;
    cudaFuncSetAttribute(qts_main, cudaFuncAttributeMaxDynamicSharedMemorySize, (int)smem);

    qts_proj<<<BATCH, 256>>>(x, Wp, bp, prep, sig, qff);
    qts_main<<<BATCH, 512, smem>>>(Wout, bout, out);
}